// round 7
// baseline (speedup 1.0000x reference)
#include <cuda_runtime.h>
#include <cuda_bf16.h>
#include <cstdint>

// ============================================================================
// Int8Linear: out[8192,4096] = x[8192,4096] @ W^T[4096,4096] + bias
// Baseline-PTX tensor path (toolchain targets sm_103 WITHOUT 'a': no tcgen05).
//
// KEY FIX (R7): the harness only marshals {float32,int32,bfloat16}; the int8
// reference weights most likely arrive PROMOTED TO INT32. Two independent GEMM
// cores (hand mma + wmma) produced bit-near-identical wrong results, proving
// the GEMM is fine and W was scrambled by reading int32 data as char4.
// We now DETECT the weight dtype on-device (first 1024 words all in [-128,127]
// as int32 => int32) and dequantize accordingly. Both paths bounds-correct.
//
//   Pass 0: detect weight dtype -> g_flag
//   Pass 1: x fp32 -> tf32 bits (cvt.rna) into scratch gA
//   Pass 2: W (int32|int8) * blockscale -> tf32 bits into scratch gB
//   Pass 3: mma.sync.m16n8k8 tf32 GEMM, CTA 128x128x32, 8 warps (4x2),
//           warp tile 32x64, 4-stage cp.async pipeline, padded SMEM rows,
//           fused bias epilogue.
// Inputs resolved BY ELEMENT COUNT (robust to metadata order).
// ============================================================================

#define M_DIM  8192
#define N_DIM  4096
#define K_DIM  4096
#define MT     128
#define NT     128
#define KT     32
#define NUM_KT (K_DIM / KT)   // 128
#define STAGES 4
#define ROWF   36             // u32 per SMEM row (32 data + 4 pad) = 144B

__device__ __align__(16) uint32_t g_xa[(size_t)M_DIM * K_DIM];  // x as tf32 bits
__device__ __align__(16) uint32_t g_wb[(size_t)N_DIM * K_DIM];  // dequant W as tf32 bits
__device__ int g_w_is_i32;                                      // weight dtype flag

// ---------------------------------------------------------------- helpers
__device__ __forceinline__ uint32_t smem_u32(const void* p) {
    uint32_t a;
    asm("{ .reg .u64 t; cvta.to.shared.u64 t, %1; cvt.u32.u64 %0, t; }" : "=r"(a) : "l"(p));
    return a;
}
__device__ __forceinline__ uint32_t f2tf32(float f) {
    uint32_t r; asm("cvt.rna.tf32.f32 %0, %1;" : "=r"(r) : "f"(f)); return r;
}
__device__ __forceinline__ void cp_async16(uint32_t dst, const void* src) {
    asm volatile("cp.async.cg.shared.global [%0], [%1], 16;" :: "r"(dst), "l"(src));
}
#define CP_COMMIT() asm volatile("cp.async.commit_group;" ::: "memory")
#define CP_WAIT2()  asm volatile("cp.async.wait_group 2;" ::: "memory")

__device__ __forceinline__ void mma_tf32(float (&d)[4], const uint32_t (&a)[4],
                                         const uint32_t (&b)[2]) {
    asm volatile(
        "mma.sync.aligned.m16n8k8.row.col.f32.tf32.tf32.f32 "
        "{%0,%1,%2,%3}, {%4,%5,%6,%7}, {%8,%9}, {%0,%1,%2,%3};"
        : "+f"(d[0]), "+f"(d[1]), "+f"(d[2]), "+f"(d[3])
        : "r"(a[0]), "r"(a[1]), "r"(a[2]), "r"(a[3]), "r"(b[0]), "r"(b[1]));
}

// ---------------------------------------------------------------- dtype probe
// If weights were promoted to int32, every 32-bit word holds a value in
// [-128,127]. For genuine int8 data, a random 32-bit word lands there with
// prob ~2^-23; over 1024 words a false "int32" verdict is impossible in
// practice. Reads only 4KB -> in-bounds for either dtype.
__global__ void detect_wtype_kernel(const int* __restrict__ w) {
    __shared__ int s_ok;
    if (threadIdx.x == 0) s_ok = 1;
    __syncthreads();
    #pragma unroll
    for (int i = 0; i < 4; i++) {
        int v = w[threadIdx.x + i * 256];
        if (v < -128 || v > 127) atomicAnd(&s_ok, 0);
    }
    __syncthreads();
    if (threadIdx.x == 0) g_w_is_i32 = s_ok;
}

// ---------------------------------------------------------------- preprocess
__global__ void cvt_x_kernel(const float4* __restrict__ x, uint4* __restrict__ out, int n4) {
    for (int i = blockIdx.x * blockDim.x + threadIdx.x; i < n4; i += gridDim.x * blockDim.x) {
        float4 v = x[i];
        uint4 o;
        o.x = f2tf32(v.x); o.y = f2tf32(v.y); o.z = f2tf32(v.z); o.w = f2tf32(v.w);
        out[i] = o;
    }
}

// Processes 4 weights per iteration; chunk i covers weights 4i..4i+3, all in
// the same 64-weight scale block -> scale index = (4i)/64 = i>>4 (both paths).
__global__ void dequant_w_kernel(const void* __restrict__ w, const float* __restrict__ scales,
                                 uint4* __restrict__ out, int n4) {
    const bool i32 = (g_w_is_i32 != 0);
    for (int i = blockIdx.x * blockDim.x + threadIdx.x; i < n4; i += gridDim.x * blockDim.x) {
        float s = __ldg(scales + (i >> 4));
        float w0, w1, w2, w3;
        if (i32) {
            int4 v = ((const int4*)w)[i];
            w0 = (float)v.x; w1 = (float)v.y; w2 = (float)v.z; w3 = (float)v.w;
        } else {
            char4 c = ((const char4*)w)[i];
            w0 = (float)c.x; w1 = (float)c.y; w2 = (float)c.z; w3 = (float)c.w;
        }
        uint4 o;
        o.x = f2tf32(s * w0); o.y = f2tf32(s * w1);
        o.z = f2tf32(s * w2); o.w = f2tf32(s * w3);
        out[i] = o;
    }
}

// ---------------------------------------------------------------- GEMM
static constexpr int A_STAGE_U32 = MT * ROWF;                 // 4608 u32
static constexpr int B_STAGE_U32 = NT * ROWF;                 // 4608 u32
static constexpr int STAGE_U32   = A_STAGE_U32 + B_STAGE_U32; // 9216 u32 = 36864 B
static constexpr int SMEM_TOTAL  = STAGES * STAGE_U32 * 4;    // 147456 B

__global__ void __launch_bounds__(256, 1)
gemm_tf32_kernel(const uint32_t* __restrict__ gA, const uint32_t* __restrict__ gB,
                 const float* __restrict__ bias, float* __restrict__ out) {
    extern __shared__ uint32_t smem[];
    const uint32_t sb = smem_u32(smem);
    const int tid = threadIdx.x, wid = tid >> 5, lid = tid & 31;
    const int wr = wid & 3;          // warp row (m): 0..3
    const int wc = wid >> 2;         // warp col (n): 0..1
    const int bm = blockIdx.y, bn = blockIdx.x;

    const uint32_t* gAt0 = gA + (size_t)bm * MT * K_DIM;
    const uint32_t* gBt0 = gB + (size_t)bn * NT * K_DIM;

    auto load_tile = [&](int t) {
        const int s = t & (STAGES - 1);
        const uint32_t sA = sb + s * STAGE_U32 * 4;
        const uint32_t sB = sA + A_STAGE_U32 * 4;
        const uint32_t* gAt = gAt0 + t * KT;
        const uint32_t* gBt = gBt0 + t * KT;
        #pragma unroll
        for (int i = 0; i < 4; i++) {           // A: 1024 16B chunks / 256 thr
            int ch = tid + i * 256;
            int r = ch >> 3, c4 = ch & 7;
            cp_async16(sA + (uint32_t)(r * ROWF * 4 + c4 * 16),
                       gAt + (size_t)r * K_DIM + c4 * 4);
        }
        #pragma unroll
        for (int i = 0; i < 4; i++) {           // B: 1024 chunks
            int ch = tid + i * 256;
            int r = ch >> 3, c4 = ch & 7;
            cp_async16(sB + (uint32_t)(r * ROWF * 4 + c4 * 16),
                       gBt + (size_t)r * K_DIM + c4 * 4);
        }
    };

    float acc[2][8][4];
    #pragma unroll
    for (int mt = 0; mt < 2; mt++)
        #pragma unroll
        for (int nt = 0; nt < 8; nt++)
            #pragma unroll
            for (int c = 0; c < 4; c++) acc[mt][nt][c] = 0.0f;

    load_tile(0); CP_COMMIT();
    load_tile(1); CP_COMMIT();
    load_tile(2); CP_COMMIT();

    const int arow = wr * 32 + (lid >> 2);   // + mt*16; +8 rows via a1/a3
    const int brow = wc * 64 + (lid >> 2);   // + nt*8
    const int kq   = lid & 3;

    for (int kt = 0; kt < NUM_KT; kt++) {
        CP_WAIT2();
        __syncthreads();

        const int tl = kt + (STAGES - 1);
        if (tl < NUM_KT) load_tile(tl);
        CP_COMMIT();

        const uint32_t* sA = smem + (kt & (STAGES - 1)) * STAGE_U32;
        const uint32_t* sB = sA + A_STAGE_U32;

        #pragma unroll
        for (int ks = 0; ks < 4; ks++) {
            const int k0 = ks * 8 + kq;
            uint32_t a[2][4];
            #pragma unroll
            for (int mt = 0; mt < 2; mt++) {
                const uint32_t* p = sA + (arow + mt * 16) * ROWF + k0;
                a[mt][0] = p[0];
                a[mt][1] = p[8 * ROWF];
                a[mt][2] = p[4];
                a[mt][3] = p[8 * ROWF + 4];
            }
            uint32_t b[8][2];
            #pragma unroll
            for (int nt = 0; nt < 8; nt++) {
                const uint32_t* p = sB + (brow + nt * 8) * ROWF + k0;
                b[nt][0] = p[0];
                b[nt][1] = p[4];
            }
            #pragma unroll
            for (int mt = 0; mt < 2; mt++)
                #pragma unroll
                for (int nt = 0; nt < 8; nt++)
                    mma_tf32(acc[mt][nt], a[mt], b[nt]);
        }
    }

    // fused bias epilogue
    const int gcol0 = bn * NT + wc * 64 + 2 * (lid & 3);
    #pragma unroll
    for (int mt = 0; mt < 2; mt++) {
        #pragma unroll
        for (int half = 0; half < 2; half++) {
            const int grow = bm * MT + wr * 32 + mt * 16 + (lid >> 2) + half * 8;
            float* op = out + (size_t)grow * N_DIM + gcol0;
            #pragma unroll
            for (int nt = 0; nt < 8; nt++) {
                const int gc = gcol0 + nt * 8;
                float2 o;
                o.x = acc[mt][nt][half * 2 + 0] + __ldg(bias + gc);
                o.y = acc[mt][nt][half * 2 + 1] + __ldg(bias + gc + 1);
                *reinterpret_cast<float2*>(op + nt * 8) = o;
            }
        }
    }
}

// ---------------------------------------------------------------- launcher
extern "C" void kernel_launch(void* const* d_in, const int* in_sizes, int n_in,
                              void* d_out, int out_size) {
    // Resolve inputs BY SIZE (unique element counts):
    //   x: 33554432 fp32, qweights: 16777216 (int8 OR int32 — detected on device),
    //   scales: 262144 fp32, bias: 4096 fp32
    const float* x      = nullptr;
    const void*  qw     = nullptr;
    const float* scales = nullptr;
    const float* bias   = nullptr;
    for (int i = 0; i < n_in; i++) {
        switch (in_sizes[i]) {
            case 33554432: x      = (const float*)d_in[i]; break;
            case 16777216: qw     = d_in[i];               break;
            case 262144:   scales = (const float*)d_in[i]; break;
            case 4096:     bias   = (const float*)d_in[i]; break;
            default: break;
        }
    }
    float* out = (float*)d_out;

    uint32_t* gA; cudaGetSymbolAddress((void**)&gA, g_xa);
    uint32_t* gB; cudaGetSymbolAddress((void**)&gB, g_wb);

    detect_wtype_kernel<<<1, 256>>>((const int*)qw);
    cvt_x_kernel<<<4096, 256>>>((const float4*)x, (uint4*)gA, (M_DIM * K_DIM) / 4);
    dequant_w_kernel<<<2048, 256>>>(qw, scales, (uint4*)gB, (N_DIM * K_DIM) / 4);

    cudaFuncSetAttribute(gemm_tf32_kernel, cudaFuncAttributeMaxDynamicSharedMemorySize, SMEM_TOTAL);
    dim3 grid(N_DIM / NT, M_DIM / MT);   // (32, 64)
    gemm_tf32_kernel<<<grid, 256, SMEM_TOTAL>>>(gA, gB, bias, out);
}

// round 9
// speedup vs baseline: 1.1488x; 1.1488x over previous
#include <cuda_runtime.h>
#include <cuda_bf16.h>
#include <cstdint>

// ============================================================================
// Int8Linear: out[8192,4096] = x[8192,4096] @ W^T[4096,4096] + bias
// R9 = R8 resubmitted unchanged (R8 bench was an infra failure, no signal).
// R8 theory: occupancy 1->2 CTAs/SM. STAGES 4->3 (SMEM 147KB->108KB),
// launch_bounds (256,2) (reg cap 128), wait_group 2->1. Compute core identical
// to R7 (PASSED, rel_err 2.94e-4; tensor=49.8% occ=12.5% -> latency-bound).
//
//   Pass 0: detect weight dtype (int8 vs int32-promoted) -> g_w_is_i32
//   Pass 1: x fp32 -> tf32 bits (cvt.rna) into scratch gA
//   Pass 2: W (int32|int8) * blockscale -> tf32 bits into scratch gB
//   Pass 3: mma.sync.m16n8k8 tf32 GEMM, CTA 128x128x32, 8 warps (4x2),
//           warp tile 32x64, 3-stage cp.async pipeline, fused bias.
// Inputs resolved BY ELEMENT COUNT (robust to metadata order).
// ============================================================================

#define M_DIM  8192
#define N_DIM  4096
#define K_DIM  4096
#define MT     128
#define NT     128
#define KT     32
#define NUM_KT (K_DIM / KT)   // 128
#define STAGES 3
#define ROWF   36             // u32 per SMEM row (32 data + 4 pad) = 144B

__device__ __align__(16) uint32_t g_xa[(size_t)M_DIM * K_DIM];  // x as tf32 bits
__device__ __align__(16) uint32_t g_wb[(size_t)N_DIM * K_DIM];  // dequant W as tf32 bits
__device__ int g_w_is_i32;                                      // weight dtype flag

// ---------------------------------------------------------------- helpers
__device__ __forceinline__ uint32_t smem_u32(const void* p) {
    uint32_t a;
    asm("{ .reg .u64 t; cvta.to.shared.u64 t, %1; cvt.u32.u64 %0, t; }" : "=r"(a) : "l"(p));
    return a;
}
__device__ __forceinline__ uint32_t f2tf32(float f) {
    uint32_t r; asm("cvt.rna.tf32.f32 %0, %1;" : "=r"(r) : "f"(f)); return r;
}
__device__ __forceinline__ void cp_async16(uint32_t dst, const void* src) {
    asm volatile("cp.async.cg.shared.global [%0], [%1], 16;" :: "r"(dst), "l"(src));
}
#define CP_COMMIT() asm volatile("cp.async.commit_group;" ::: "memory")
#define CP_WAIT1()  asm volatile("cp.async.wait_group 1;" ::: "memory")

__device__ __forceinline__ void mma_tf32(float (&d)[4], const uint32_t (&a)[4],
                                         const uint32_t (&b)[2]) {
    asm volatile(
        "mma.sync.aligned.m16n8k8.row.col.f32.tf32.tf32.f32 "
        "{%0,%1,%2,%3}, {%4,%5,%6,%7}, {%8,%9}, {%0,%1,%2,%3};"
        : "+f"(d[0]), "+f"(d[1]), "+f"(d[2]), "+f"(d[3])
        : "r"(a[0]), "r"(a[1]), "r"(a[2]), "r"(a[3]), "r"(b[0]), "r"(b[1]));
}

// ---------------------------------------------------------------- dtype probe
__global__ void detect_wtype_kernel(const int* __restrict__ w) {
    __shared__ int s_ok;
    if (threadIdx.x == 0) s_ok = 1;
    __syncthreads();
    #pragma unroll
    for (int i = 0; i < 4; i++) {
        int v = w[threadIdx.x + i * 256];
        if (v < -128 || v > 127) atomicAnd(&s_ok, 0);
    }
    __syncthreads();
    if (threadIdx.x == 0) g_w_is_i32 = s_ok;
}

// ---------------------------------------------------------------- preprocess
__global__ void cvt_x_kernel(const float4* __restrict__ x, uint4* __restrict__ out, int n4) {
    for (int i = blockIdx.x * blockDim.x + threadIdx.x; i < n4; i += gridDim.x * blockDim.x) {
        float4 v = x[i];
        uint4 o;
        o.x = f2tf32(v.x); o.y = f2tf32(v.y); o.z = f2tf32(v.z); o.w = f2tf32(v.w);
        out[i] = o;
    }
}

__global__ void dequant_w_kernel(const void* __restrict__ w, const float* __restrict__ scales,
                                 uint4* __restrict__ out, int n4) {
    const bool i32 = (g_w_is_i32 != 0);
    for (int i = blockIdx.x * blockDim.x + threadIdx.x; i < n4; i += gridDim.x * blockDim.x) {
        float s = __ldg(scales + (i >> 4));
        float w0, w1, w2, w3;
        if (i32) {
            int4 v = ((const int4*)w)[i];
            w0 = (float)v.x; w1 = (float)v.y; w2 = (float)v.z; w3 = (float)v.w;
        } else {
            char4 c = ((const char4*)w)[i];
            w0 = (float)c.x; w1 = (float)c.y; w2 = (float)c.z; w3 = (float)c.w;
        }
        uint4 o;
        o.x = f2tf32(s * w0); o.y = f2tf32(s * w1);
        o.z = f2tf32(s * w2); o.w = f2tf32(s * w3);
        out[i] = o;
    }
}

// ---------------------------------------------------------------- GEMM
static constexpr int A_STAGE_U32 = MT * ROWF;                 // 4608 u32
static constexpr int B_STAGE_U32 = NT * ROWF;                 // 4608 u32
static constexpr int STAGE_U32   = A_STAGE_U32 + B_STAGE_U32; // 9216 u32 = 36864 B
static constexpr int SMEM_TOTAL  = STAGES * STAGE_U32 * 4;    // 110592 B -> 2 CTA/SM

__global__ void __launch_bounds__(256, 2)
gemm_tf32_kernel(const uint32_t* __restrict__ gA, const uint32_t* __restrict__ gB,
                 const float* __restrict__ bias, float* __restrict__ out) {
    extern __shared__ uint32_t smem[];
    const uint32_t sb = smem_u32(smem);
    const int tid = threadIdx.x, wid = tid >> 5, lid = tid & 31;
    const int wr = wid & 3;          // warp row (m): 0..3
    const int wc = wid >> 2;         // warp col (n): 0..1
    const int bm = blockIdx.y, bn = blockIdx.x;

    const uint32_t* gAt0 = gA + (size_t)bm * MT * K_DIM;
    const uint32_t* gBt0 = gB + (size_t)bn * NT * K_DIM;

    // loader with explicit stage (STAGES=3, not a power of two)
    auto load_tile = [&](int t, int s) {
        const uint32_t sA = sb + s * STAGE_U32 * 4;
        const uint32_t sB = sA + A_STAGE_U32 * 4;
        const uint32_t* gAt = gAt0 + t * KT;
        const uint32_t* gBt = gBt0 + t * KT;
        #pragma unroll
        for (int i = 0; i < 4; i++) {           // A: 1024 16B chunks / 256 thr
            int ch = tid + i * 256;
            int r = ch >> 3, c4 = ch & 7;
            cp_async16(sA + (uint32_t)(r * ROWF * 4 + c4 * 16),
                       gAt + (size_t)r * K_DIM + c4 * 4);
        }
        #pragma unroll
        for (int i = 0; i < 4; i++) {           // B: 1024 chunks
            int ch = tid + i * 256;
            int r = ch >> 3, c4 = ch & 7;
            cp_async16(sB + (uint32_t)(r * ROWF * 4 + c4 * 16),
                       gBt + (size_t)r * K_DIM + c4 * 4);
        }
    };

    float acc[2][8][4];
    #pragma unroll
    for (int mt = 0; mt < 2; mt++)
        #pragma unroll
        for (int nt = 0; nt < 8; nt++)
            #pragma unroll
            for (int c = 0; c < 4; c++) acc[mt][nt][c] = 0.0f;

    load_tile(0, 0); CP_COMMIT();
    load_tile(1, 1); CP_COMMIT();

    const int arow = wr * 32 + (lid >> 2);   // + mt*16; +8 rows via a1/a3
    const int brow = wc * 64 + (lid >> 2);   // + nt*8
    const int kq   = lid & 3;

    int cs = 0;   // compute stage (kt % 3)
    int ls = 2;   // stage for tile kt+2
    for (int kt = 0; kt < NUM_KT; kt++) {
        CP_WAIT1();                 // tile kt resident (1 group may stay in flight)
        __syncthreads();

        const int tl = kt + 2;
        if (tl < NUM_KT) load_tile(tl, ls);   // overlap next loads with compute
        CP_COMMIT();

        const uint32_t* sA = smem + cs * STAGE_U32;
        const uint32_t* sB = sA + A_STAGE_U32;

        #pragma unroll
        for (int ks = 0; ks < 4; ks++) {
            const int k0 = ks * 8 + kq;
            uint32_t a[2][4];
            #pragma unroll
            for (int mt = 0; mt < 2; mt++) {
                const uint32_t* p = sA + (arow + mt * 16) * ROWF + k0;
                a[mt][0] = p[0];
                a[mt][1] = p[8 * ROWF];
                a[mt][2] = p[4];
                a[mt][3] = p[8 * ROWF + 4];
            }
            uint32_t b[8][2];
            #pragma unroll
            for (int nt = 0; nt < 8; nt++) {
                const uint32_t* p = sB + (brow + nt * 8) * ROWF + k0;
                b[nt][0] = p[0];
                b[nt][1] = p[4];
            }
            #pragma unroll
            for (int mt = 0; mt < 2; mt++)
                #pragma unroll
                for (int nt = 0; nt < 8; nt++)
                    mma_tf32(acc[mt][nt], a[mt], b[nt]);
        }

        if (++cs == STAGES) cs = 0;
        if (++ls == STAGES) ls = 0;
    }

    // fused bias epilogue
    const int gcol0 = bn * NT + wc * 64 + 2 * (lid & 3);
    #pragma unroll
    for (int mt = 0; mt < 2; mt++) {
        #pragma unroll
        for (int half = 0; half < 2; half++) {
            const int grow = bm * MT + wr * 32 + mt * 16 + (lid >> 2) + half * 8;
            float* op = out + (size_t)grow * N_DIM + gcol0;
            #pragma unroll
            for (int nt = 0; nt < 8; nt++) {
                const int gc = gcol0 + nt * 8;
                float2 o;
                o.x = acc[mt][nt][half * 2 + 0] + __ldg(bias + gc);
                o.y = acc[mt][nt][half * 2 + 1] + __ldg(bias + gc + 1);
                *reinterpret_cast<float2*>(op + nt * 8) = o;
            }
        }
    }
}

// ---------------------------------------------------------------- launcher
extern "C" void kernel_launch(void* const* d_in, const int* in_sizes, int n_in,
                              void* d_out, int out_size) {
    // Resolve inputs BY SIZE (unique element counts):
    //   x: 33554432 fp32, qweights: 16777216 (int8 OR int32 — detected on device),
    //   scales: 262144 fp32, bias: 4096 fp32
    const float* x      = nullptr;
    const void*  qw     = nullptr;
    const float* scales = nullptr;
    const float* bias   = nullptr;
    for (int i = 0; i < n_in; i++) {
        switch (in_sizes[i]) {
            case 33554432: x      = (const float*)d_in[i]; break;
            case 16777216: qw     = d_in[i];               break;
            case 262144:   scales = (const float*)d_in[i]; break;
            case 4096:     bias   = (const float*)d_in[i]; break;
            default: break;
        }
    }
    float* out = (float*)d_out;

    uint32_t* gA; cudaGetSymbolAddress((void**)&gA, g_xa);
    uint32_t* gB; cudaGetSymbolAddress((void**)&gB, g_wb);

    detect_wtype_kernel<<<1, 256>>>((const int*)qw);
    cvt_x_kernel<<<4096, 256>>>((const float4*)x, (uint4*)gA, (M_DIM * K_DIM) / 4);
    dequant_w_kernel<<<2048, 256>>>(qw, scales, (uint4*)gB, (N_DIM * K_DIM) / 4);

    cudaFuncSetAttribute(gemm_tf32_kernel, cudaFuncAttributeMaxDynamicSharedMemorySize, SMEM_TOTAL);
    dim3 grid(N_DIM / NT, M_DIM / MT);   // (32, 64)
    gemm_tf32_kernel<<<grid, 256, SMEM_TOTAL>>>(gA, gB, bias, out);
}

// round 10
// speedup vs baseline: 1.2059x; 1.0497x over previous
#include <cuda_runtime.h>
#include <cuda_bf16.h>
#include <cstdint>

// ============================================================================
// Int8Linear: out[8192,4096] = x[8192,4096] @ W^T[4096,4096] + bias
// R10: vectorized fragment loads. Scratch is stored with each 16-k block
// permuted (phys = 4*(k%4) + k/4), so ONE LDS.128 per thread yields the tf32
// fragment operands for TWO k8 MMA steps. 96 LDS.32 -> 24 LDS.128 per k-tile.
// XOR swizzle (c ^= (row&1)<<2) keeps all SMEM phases conflict-free with NO
// row padding (32KB/stage). Accumulation order is bit-identical to R9
// (rel_err canary: must equal 2.937228e-4 exactly).
//
//   Pass 0: detect weight dtype (int8 vs int32-promoted) -> g_w_is_i32
//   Pass 1: x fp32 -> tf32 bits, 16-k-permuted, into scratch gA
//   Pass 2: W dequant -> tf32 bits, 16-k-permuted, into scratch gB
//   Pass 3: mma.sync m16n8k8 tf32 GEMM, CTA 128x128x32, 8 warps (4x2),
//           3-stage cp.async pipeline, 2 CTA/SM, fused bias.
// ============================================================================

#define M_DIM  8192
#define N_DIM  4096
#define K_DIM  4096
#define MT     128
#define NT     128
#define KT     32
#define NUM_KT (K_DIM / KT)   // 128
#define STAGES 3

__device__ __align__(16) uint32_t g_xa[(size_t)M_DIM * K_DIM];  // x, tf32, k-permuted
__device__ __align__(16) uint32_t g_wb[(size_t)N_DIM * K_DIM];  // W,  tf32, k-permuted
__device__ int g_w_is_i32;

// ---------------------------------------------------------------- helpers
__device__ __forceinline__ uint32_t smem_u32(const void* p) {
    uint32_t a;
    asm("{ .reg .u64 t; cvta.to.shared.u64 t, %1; cvt.u32.u64 %0, t; }" : "=r"(a) : "l"(p));
    return a;
}
__device__ __forceinline__ uint32_t f2tf32(float f) {
    uint32_t r; asm("cvt.rna.tf32.f32 %0, %1;" : "=r"(r) : "f"(f)); return r;
}
__device__ __forceinline__ void cp_async16(uint32_t dst, const void* src) {
    asm volatile("cp.async.cg.shared.global [%0], [%1], 16;" :: "r"(dst), "l"(src));
}
#define CP_COMMIT() asm volatile("cp.async.commit_group;" ::: "memory")
#define CP_WAIT1()  asm volatile("cp.async.wait_group 1;" ::: "memory")

__device__ __forceinline__ void mma_tf32(float (&d)[4], const uint32_t (&a)[4],
                                         const uint32_t (&b)[2]) {
    asm volatile(
        "mma.sync.aligned.m16n8k8.row.col.f32.tf32.tf32.f32 "
        "{%0,%1,%2,%3}, {%4,%5,%6,%7}, {%8,%9}, {%0,%1,%2,%3};"
        : "+f"(d[0]), "+f"(d[1]), "+f"(d[2]), "+f"(d[3])
        : "r"(a[0]), "r"(a[1]), "r"(a[2]), "r"(a[3]), "r"(b[0]), "r"(b[1]));
}

// ---------------------------------------------------------------- dtype probe
__global__ void detect_wtype_kernel(const int* __restrict__ w) {
    __shared__ int s_ok;
    if (threadIdx.x == 0) s_ok = 1;
    __syncthreads();
    #pragma unroll
    for (int i = 0; i < 4; i++) {
        int v = w[threadIdx.x + i * 256];
        if (v < -128 || v > 127) atomicAnd(&s_ok, 0);
    }
    __syncthreads();
    if (threadIdx.x == 0) g_w_is_i32 = s_ok;
}

// ---------------------------------------------------------------- preprocess
// Each thread handles one 16-k block: read 4 float4 (logical), write 4 uint4
// (phys): phys float4 p = (w[p], w[p+4], w[p+8], w[p+12])  [4x4 transpose].
__global__ void cvt_x_kernel(const float4* __restrict__ x, uint4* __restrict__ out, int nblk) {
    for (int b = blockIdx.x * blockDim.x + threadIdx.x; b < nblk; b += gridDim.x * blockDim.x) {
        float4 v0 = x[b * 4 + 0], v1 = x[b * 4 + 1], v2 = x[b * 4 + 2], v3 = x[b * 4 + 3];
        uint4 o;
        o.x = f2tf32(v0.x); o.y = f2tf32(v1.x); o.z = f2tf32(v2.x); o.w = f2tf32(v3.x);
        out[b * 4 + 0] = o;
        o.x = f2tf32(v0.y); o.y = f2tf32(v1.y); o.z = f2tf32(v2.y); o.w = f2tf32(v3.y);
        out[b * 4 + 1] = o;
        o.x = f2tf32(v0.z); o.y = f2tf32(v1.z); o.z = f2tf32(v2.z); o.w = f2tf32(v3.z);
        out[b * 4 + 2] = o;
        o.x = f2tf32(v0.w); o.y = f2tf32(v1.w); o.z = f2tf32(v2.w); o.w = f2tf32(v3.w);
        out[b * 4 + 3] = o;
    }
}

__global__ void dequant_w_kernel(const void* __restrict__ wsrc, const float* __restrict__ scales,
                                 uint4* __restrict__ out, int nblk) {
    const bool i32 = (g_w_is_i32 != 0);
    for (int b = blockIdx.x * blockDim.x + threadIdx.x; b < nblk; b += gridDim.x * blockDim.x) {
        float s = __ldg(scales + (b >> 2));   // 64 weights per scale = 4 blocks of 16
        float w[16];
        if (i32) {
            const int4* p = (const int4*)wsrc + b * 4;
            #pragma unroll
            for (int j = 0; j < 4; j++) {
                int4 v = p[j];
                w[j * 4 + 0] = (float)v.x; w[j * 4 + 1] = (float)v.y;
                w[j * 4 + 2] = (float)v.z; w[j * 4 + 3] = (float)v.w;
            }
        } else {
            uint4 raw = ((const uint4*)wsrc)[b];
            uint32_t ws[4] = {raw.x, raw.y, raw.z, raw.w};
            #pragma unroll
            for (int j = 0; j < 4; j++)
                #pragma unroll
                for (int t = 0; t < 4; t++)
                    w[j * 4 + t] = (float)(int8_t)((ws[j] >> (8 * t)) & 0xFF);
        }
        #pragma unroll
        for (int p = 0; p < 4; p++) {
            uint4 o;
            o.x = f2tf32(s * w[p]);      o.y = f2tf32(s * w[p + 4]);
            o.z = f2tf32(s * w[p + 8]);  o.w = f2tf32(s * w[p + 12]);
            out[b * 4 + p] = o;
        }
    }
}

// ---------------------------------------------------------------- GEMM
static constexpr int A_STAGE_U32 = MT * KT;                   // 4096 u32 = 16KB
static constexpr int B_STAGE_U32 = NT * KT;                   // 4096 u32
static constexpr int STAGE_U32   = A_STAGE_U32 + B_STAGE_U32; // 8192 u32 = 32KB
static constexpr int SMEM_TOTAL  = STAGES * STAGE_U32 * 4;    // 98304 B -> 2 CTA/SM

__global__ void __launch_bounds__(256, 2)
gemm_tf32_kernel(const uint32_t* __restrict__ gA, const uint32_t* __restrict__ gB,
                 const float* __restrict__ bias, float* __restrict__ out) {
    extern __shared__ uint32_t smem[];
    const uint32_t sb = smem_u32(smem);
    const int tid = threadIdx.x, wid = tid >> 5, lid = tid & 31;
    const int wr = wid & 3;          // warp row (m): 0..3
    const int wc = wid >> 2;         // warp col (n): 0..1
    const int bm = blockIdx.y, bn = blockIdx.x;

    const uint32_t* gAt0 = gA + (size_t)bm * MT * K_DIM;
    const uint32_t* gBt0 = gB + (size_t)bn * NT * K_DIM;

    // loader: rows of 32 u32 = 8 float4; phys col c4 stored at c4 ^ ((r&1)<<2)
    auto load_tile = [&](int t, int s) {
        const uint32_t sA = sb + s * STAGE_U32 * 4;
        const uint32_t sB = sA + A_STAGE_U32 * 4;
        const uint32_t* gAt = gAt0 + t * KT;
        const uint32_t* gBt = gBt0 + t * KT;
        #pragma unroll
        for (int i = 0; i < 4; i++) {           // A: 1024 16B chunks / 256 thr
            int ch = tid + i * 256;
            int r = ch >> 3, c4 = ch & 7;
            int cs4 = c4 ^ ((r & 1) << 2);
            cp_async16(sA + (uint32_t)((r * 8 + cs4) * 16),
                       gAt + (size_t)r * K_DIM + c4 * 4);
        }
        #pragma unroll
        for (int i = 0; i < 4; i++) {           // B: 1024 chunks
            int ch = tid + i * 256;
            int r = ch >> 3, c4 = ch & 7;
            int cs4 = c4 ^ ((r & 1) << 2);
            cp_async16(sB + (uint32_t)((r * 8 + cs4) * 16),
                       gBt + (size_t)r * K_DIM + c4 * 4);
        }
    };

    float acc[2][8][4];
    #pragma unroll
    for (int mt = 0; mt < 2; mt++)
        #pragma unroll
        for (int nt = 0; nt < 8; nt++)
            #pragma unroll
            for (int c = 0; c < 4; c++) acc[mt][nt][c] = 0.0f;

    load_tile(0, 0); CP_COMMIT();
    load_tile(1, 1); CP_COMMIT();

    const int arow = wr * 32 + (lid >> 2);   // + mt*16 + h*8
    const int brow = wc * 64 + (lid >> 2);   // + nt*8
    const int kq   = lid & 3;

    int cs = 0;   // compute stage
    int ls = 2;   // load stage for tile kt+2
    for (int kt = 0; kt < NUM_KT; kt++) {
        CP_WAIT1();
        __syncthreads();

        const int tl = kt + 2;
        if (tl < NUM_KT) load_tile(tl, ls);
        CP_COMMIT();

        const uint4* sA4 = reinterpret_cast<const uint4*>(smem + cs * STAGE_U32);
        const uint4* sB4 = reinterpret_cast<const uint4*>(smem + cs * STAGE_U32 + A_STAGE_U32);

        #pragma unroll
        for (int ks2 = 0; ks2 < 2; ks2++) {      // two 16-k halves of KT=32
            // A fragments: one LDS.128 covers 2 k8 steps
            uint32_t Ar[2][2][4];
            #pragma unroll
            for (int mt = 0; mt < 2; mt++)
                #pragma unroll
                for (int h = 0; h < 2; h++) {
                    int row = arow + mt * 16 + h * 8;
                    int c = (ks2 * 4 + kq) ^ ((row & 1) << 2);
                    uint4 v = sA4[row * 8 + c];
                    Ar[mt][h][0] = v.x; Ar[mt][h][1] = v.y;
                    Ar[mt][h][2] = v.z; Ar[mt][h][3] = v.w;
                }
            #pragma unroll
            for (int ng = 0; ng < 2; ng++) {     // B in groups of 4 (reg pressure)
                uint32_t Br[4][4];
                #pragma unroll
                for (int j = 0; j < 4; j++) {
                    int row = brow + (ng * 4 + j) * 8;
                    int c = (ks2 * 4 + kq) ^ ((row & 1) << 2);
                    uint4 v = sB4[row * 8 + c];
                    Br[j][0] = v.x; Br[j][1] = v.y; Br[j][2] = v.z; Br[j][3] = v.w;
                }
                #pragma unroll
                for (int sub = 0; sub < 2; sub++) {   // the 2 k8 steps
                    #pragma unroll
                    for (int mt = 0; mt < 2; mt++) {
                        uint32_t a[4] = {Ar[mt][0][2 * sub], Ar[mt][1][2 * sub],
                                         Ar[mt][0][2 * sub + 1], Ar[mt][1][2 * sub + 1]};
                        #pragma unroll
                        for (int j = 0; j < 4; j++) {
                            uint32_t b[2] = {Br[j][2 * sub], Br[j][2 * sub + 1]};
                            mma_tf32(acc[mt][ng * 4 + j], a, b);
                        }
                    }
                }
            }
        }

        if (++cs == STAGES) cs = 0;
        if (++ls == STAGES) ls = 0;
    }

    // fused bias epilogue
    const int gcol0 = bn * NT + wc * 64 + 2 * (lid & 3);
    #pragma unroll
    for (int mt = 0; mt < 2; mt++) {
        #pragma unroll
        for (int half = 0; half < 2; half++) {
            const int grow = bm * MT + wr * 32 + mt * 16 + (lid >> 2) + half * 8;
            float* op = out + (size_t)grow * N_DIM + gcol0;
            #pragma unroll
            for (int nt = 0; nt < 8; nt++) {
                const int gc = gcol0 + nt * 8;
                float2 o;
                o.x = acc[mt][nt][half * 2 + 0] + __ldg(bias + gc);
                o.y = acc[mt][nt][half * 2 + 1] + __ldg(bias + gc + 1);
                *reinterpret_cast<float2*>(op + nt * 8) = o;
            }
        }
    }
}

// ---------------------------------------------------------------- launcher
extern "C" void kernel_launch(void* const* d_in, const int* in_sizes, int n_in,
                              void* d_out, int out_size) {
    // Resolve inputs BY SIZE (unique element counts).
    const float* x      = nullptr;
    const void*  qw     = nullptr;
    const float* scales = nullptr;
    const float* bias   = nullptr;
    for (int i = 0; i < n_in; i++) {
        switch (in_sizes[i]) {
            case 33554432: x      = (const float*)d_in[i]; break;
            case 16777216: qw     = d_in[i];               break;
            case 262144:   scales = (const float*)d_in[i]; break;
            case 4096:     bias   = (const float*)d_in[i]; break;
            default: break;
        }
    }
    float* out = (float*)d_out;

    uint32_t* gA; cudaGetSymbolAddress((void**)&gA, g_xa);
    uint32_t* gB; cudaGetSymbolAddress((void**)&gB, g_wb);

    detect_wtype_kernel<<<1, 256>>>((const int*)qw);
    cvt_x_kernel<<<4096, 256>>>((const float4*)x, (uint4*)gA, (M_DIM * K_DIM) / 16);
    dequant_w_kernel<<<2048, 256>>>(qw, scales, (uint4*)gB, (N_DIM * K_DIM) / 16);

    cudaFuncSetAttribute(gemm_tf32_kernel, cudaFuncAttributeMaxDynamicSharedMemorySize, SMEM_TOTAL);
    dim3 grid(N_DIM / NT, M_DIM / MT);   // (32, 64)
    gemm_tf32_kernel<<<grid, 256, SMEM_TOTAL>>>(gA, gB, bias, out);
}